// round 12
// baseline (speedup 1.0000x reference)
#include <cuda_runtime.h>
#include <cuda_fp16.h>
#include <cstdint>

#define B       128
#define T       256
#define H       1024
#define NG      4096
#define THREADS 512
#define CTAS    128
#define JPC     8
#define NKQ     16          // k16-steps per warp (k-quarter of 1024)

// ---- persistent device state ----
// h (fp16) in mma-A-fragment layout: [buf][K*256 + m*32 + lane] (uint4)
__device__ uint4 g_hf[2][64 * 256];
__device__ unsigned int g_bar_arrive = 0;
__device__ volatile unsigned int g_bar_gen = 0;

// ---- SMEM layout (bytes) ----
#define U_RSTRIDE 2064      // U^T rows padded -> conflict-free ldmatrix
#define OFF_UHI 0           // 66048 (single fp16)
#define OFF_ZX  66048       // 65536  z partial exchange (4-way kq reduction)
#define OFF_W   131584      // 4*32 f32
#define OFF_BS  132096      // 32 f32
#define SMEM_TOTAL 132224

__device__ __forceinline__ uint32_t smem_u32(const void* p) {
    uint32_t a;
    asm("{ .reg .u64 t; cvta.to.shared.u64 t, %1; cvt.u32.u64 %0, t; }"
        : "=r"(a) : "l"(p));
    return a;
}

#define LDSM_X4(r0, r1, r2, r3, a) \
    asm volatile("ldmatrix.sync.aligned.m8n8.x4.shared.b16 {%0,%1,%2,%3}, [%4];" \
                 : "=r"(r0), "=r"(r1), "=r"(r2), "=r"(r3) : "r"(a))

#define MMA_F16(d, a0, a1, a2, a3, b0, b1) \
    asm volatile("mma.sync.aligned.m16n8k16.row.col.f32.f16.f16.f32 " \
                 "{%0,%1,%2,%3}, {%4,%5,%6,%7}, {%8,%9}, {%0,%1,%2,%3};" \
                 : "+f"((d)[0]), "+f"((d)[1]), "+f"((d)[2]), "+f"((d)[3]) \
                 : "r"(a0), "r"(a1), "r"(a2), "r"(a3), "r"(b0), "r"(b1))

__device__ __forceinline__ void grid_barrier() {
    __syncthreads();
    __threadfence();
    if (threadIdx.x == 0) {
        unsigned int gen = g_bar_gen;
        if (atomicAdd(&g_bar_arrive, 1u) == CTAS - 1) {
            g_bar_arrive = 0;
            __threadfence();
            g_bar_gen = gen + 1;
        } else {
            while (g_bar_gen == gen) { }
        }
    }
    __syncthreads();
}

__device__ __forceinline__ uint32_t packh(__half a, __half b) {
    return (uint32_t)__half_as_ushort(a) | ((uint32_t)__half_as_ushort(b) << 16);
}

__global__ void __launch_bounds__(THREADS, 1)
lstm_f16_kernel(const float* __restrict__ seq,
                const float* __restrict__ W,
                const float* __restrict__ U,
                const float* __restrict__ bias,
                float* __restrict__ out,
                int write_extras)
{
    extern __shared__ __align__(1024) uint8_t smem[];
    const uint32_t sbase = smem_u32(smem);
    const int tid = threadIdx.x;
    const int wid = tid >> 5;
    const int lid = tid & 31;
    const int mg  = wid & 3;          // m-group: m-tiles 2mg, 2mg+1
    const int kq  = wid >> 2;         // k-quarter 0..3
    const int cta = blockIdx.x;
    const int j0  = cta * JPC;
    const int Kc  = cta >> 1;         // frag kstep this CTA's j-columns land in
    const int codd = cta & 1;

    float*  Wsl = (float*)(smem + OFF_W);
    float*  bsl = (float*)(smem + OFF_BS);
    float4* zx4 = (float4*)(smem + OFF_ZX);
    const float2* zx2 = (const float2*)(smem + OFF_ZX);

    // ---------------- prologue ----------------
    // U slice -> U^T fp16 (row n = gate*8+jj, k contiguous)
    for (int idx = tid; idx < 32 * H; idx += THREADS) {
        int k = idx >> 5, n = idx & 31;
        int gcol = ((n >> 3) << 10) + j0 + (n & 7);
        *(__half*)(smem + OFF_UHI + n * U_RSTRIDE + k * 2) =
            __float2half_rn(U[(size_t)k * NG + gcol]);
    }
    if (tid < 4 * 32) {
        int f = tid >> 5, cc = tid & 31;
        Wsl[tid] = W[f * NG + ((cc >> 3) << 10) + j0 + (cc & 7)];
    }
    if (tid < 32)
        bsl[tid] = bias[((tid >> 3) << 10) + j0 + (tid & 7)];
    // zero-init this CTA's h-frag region in buf 0 (its 8B half of each elem)
    if (tid < 256) {
        int mm = tid >> 5, lane = tid & 31;
        ((uint2*)&g_hf[0][Kc * 256 + mm * 32 + lane])[codd] = make_uint2(0u, 0u);
    }
    grid_barrier();

    // ---- B ldmatrix lane geometry ----
    const int lr  = lid & 7;
    const int grp = lid >> 3;
    const uint32_t boff = (uint32_t)(((grp >> 1) * 8 + lr) * U_RSTRIDE + (grp & 1) * 16);
    const uint32_t uhib = sbase + OFF_UHI;

    const int rq = lid >> 2;
    const int jp = (lid & 3) * 2;
    const int m0 = 2 * mg;            // first of this warp's two m-tiles
    const int Kbase = 16 * kq;

    // epilogue ownership: octet o covers rows 8o..8o+7
    const int o    = 4 * mg + kq;
    const int mt_o = o >> 1;          // owned m-tile
    const int half = o & 1;           // row half within the m16 tile
    const int mtl_o = kq >> 1;        // local index of owned m-tile
    const int bq   = 8 * o + rq;      // owned batch row

    float c_reg[2];
    c_reg[0] = 0.0f; c_reg[1] = 0.0f;

    const size_t OFF_HL = (size_t)B * T * H;
    const size_t OFF_CL = OFF_HL + (size_t)B * H;

    for (int t = 0; t < T; ++t) {
        const int rb = t & 1, wbuf = rb ^ 1;
        const uint4* HF = g_hf[rb];

        float S1[2][4][4];
#pragma unroll
        for (int mtl = 0; mtl < 2; ++mtl)
#pragma unroll
            for (int n = 0; n < 4; ++n)
#pragma unroll
                for (int r = 0; r < 4; ++r) S1[mtl][n][r] = 0.f;

        // ---- flattened GEMM: 32 units = (ks 0..15) x (mtl 0..1) ----
        // A: 6-deep register ring (3 ks of L2 latency cover)
        // B: 2-deep ldmatrix double-buffer
        uint4 rA[6];
#pragma unroll
        for (int u = 0; u < 6; ++u)
            rA[u] = __ldcg(HF + (Kbase + (u >> 1)) * 256
                              + (m0 + (u & 1)) * 32 + lid);
        uint32_t bb[2][8];
        {
            const uint32_t Kb = (uint32_t)Kbase * 32u;
            LDSM_X4(bb[0][0], bb[0][1], bb[0][2], bb[0][3], uhib + boff + Kb);
            LDSM_X4(bb[0][4], bb[0][5], bb[0][6], bb[0][7],
                    uhib + boff + 16u * U_RSTRIDE + Kb);
        }

#pragma unroll
        for (int u = 0; u < 32; ++u) {
            const int ks   = u >> 1;
            const int mtl  = u & 1;
            const int slot = u % 6;
            const uint4 A  = rA[slot];          // copy before slot reuse
            if (u + 6 < 32)
                rA[slot] = __ldcg(HF + (Kbase + ((u + 6) >> 1)) * 256
                                     + (m0 + ((u + 6) & 1)) * 32 + lid);
            if (mtl == 0 && ks + 1 < NKQ) {
                const int bn = (ks + 1) & 1;
                const uint32_t Kb = (uint32_t)(Kbase + ks + 1) * 32u;
                LDSM_X4(bb[bn][0], bb[bn][1], bb[bn][2], bb[bn][3],
                        uhib + boff + Kb);
                LDSM_X4(bb[bn][4], bb[bn][5], bb[bn][6], bb[bn][7],
                        uhib + boff + 16u * U_RSTRIDE + Kb);
            }
            const int bc = ks & 1;
#pragma unroll
            for (int n = 0; n < 4; ++n)
                MMA_F16(S1[mtl][n], A.x, A.y, A.z, A.w,
                        bb[bc][2 * n], bb[bc][2 * n + 1]);
        }

        // ---- 4-way kq reduction: publish all partials ----
#pragma unroll
        for (int mtl = 0; mtl < 2; ++mtl) {
            const int mt = m0 + mtl;
#pragma unroll
            for (int n = 0; n < 4; ++n)
                zx4[((kq * 8 + mt) * 4 + n) * 32 + lid] =
                    make_float4(S1[mtl][n][0], S1[mtl][n][1],
                                S1[mtl][n][2], S1[mtl][n][3]);
        }
        __syncthreads();

        // ---- epilogue: all 16 warps, 1 row-octet x 2 cells each ----
        {
            float zt[4][2];
#pragma unroll
            for (int n = 0; n < 4; ++n) {
                zt[n][0] = S1[mtl_o][n][2 * half];
                zt[n][1] = S1[mtl_o][n][2 * half + 1];
#pragma unroll
                for (int qq = 0; qq < 4; ++qq) {
                    if (qq == kq) continue;
                    float2 p = zx2[(((qq * 8 + mt_o) * 4 + n) * 32 + lid) * 2 + half];
                    zt[n][0] += p.x;
                    zt[n][1] += p.y;
                }
            }
            const float4 sv = __ldg((const float4*)seq + ((size_t)bq * T + t));

            float hv2[2];
#pragma unroll
            for (int e = 0; e < 2; ++e) {
                const int jj = jp + e;
                float z[4];
#pragma unroll
                for (int g = 0; g < 4; ++g) {
                    const int cc = g * 8 + jj;
                    z[g] = zt[g][e] + bsl[cc]
                         + sv.x * Wsl[cc] + sv.y * Wsl[32 + cc]
                         + sv.z * Wsl[64 + cc] + sv.w * Wsl[96 + cc];
                }
                float ig = 1.0f / (1.0f + __expf(-z[0]));
                float fg = 1.0f / (1.0f + __expf(-z[1]));
                float gg = fmaxf(z[2], 0.0f);
                float og = 1.0f / (1.0f + __expf(-z[3]));
                float cn = fg * c_reg[e] + ig * gg;
                c_reg[e] = cn;
                float hv = og * fmaxf(cn, 0.0f);
                hv2[e] = hv;
                out[((size_t)bq * T + t) * H + j0 + jj] = hv;
                if (write_extras && t == T - 1) {
                    out[OFF_HL + (size_t)bq * H + j0 + jj] = hv;
                    out[OFF_CL + (size_t)bq * H + j0 + jj] = cn;
                }
            }
            // h-frag writeback: one 32-bit word per warp
            ((uint32_t*)&g_hf[wbuf][Kc * 256 + mt_o * 32 + lid])[codd * 2 + half] =
                packh(__float2half_rn(hv2[0]), __float2half_rn(hv2[1]));
        }
        grid_barrier();   // h complete chip-wide before next step's loads
    }
}

extern "C" void kernel_launch(void* const* d_in, const int* in_sizes, int n_in,
                              void* d_out, int out_size)
{
    const float* seq  = (const float*)d_in[0];   // [128,256,4]
    const float* W    = (const float*)d_in[1];   // [4,4096]
    const float* U    = (const float*)d_in[2];   // [1024,4096]
    const float* bias = (const float*)d_in[3];   // [4096]
    float* out = (float*)d_out;

    long long need = (long long)B * T * H + 2LL * B * H;
    int write_extras = ((long long)out_size >= need) ? 1 : 0;

    cudaFuncSetAttribute(lstm_f16_kernel,
                         cudaFuncAttributeMaxDynamicSharedMemorySize, SMEM_TOTAL);
    lstm_f16_kernel<<<CTAS, THREADS, SMEM_TOTAL>>>(seq, W, U, bias, out,
                                                   write_extras);
}